// round 4
// baseline (speedup 1.0000x reference)
#include <cuda_runtime.h>

// Scratch: [0]=sum|r-t|, [1]=sum g, [2]=sum|g-mu|
// Zero at module load; reset by the exit-ticket CTA each run (replay-safe).
__device__ double g_acc[3];
// Monotone counters (never reset -> no reset/spin race across graph replays)
__device__ unsigned int g_bar[2];   // [0] mid grid barrier, [1] exit ticket

static __device__ __forceinline__ float warp_reduce(float v) {
    #pragma unroll
    for (int o = 16; o > 0; o >>= 1) v += __shfl_down_sync(0xFFFFFFFFu, v, o);
    return v;
}

__global__ void __launch_bounds__(512, 3)
k_fused(const float4* __restrict__ r, const float4* __restrict__ t,
        const float4* __restrict__ g, float* __restrict__ out,
        int n4, unsigned int nCTA) {
    const int tid    = blockIdx.x * blockDim.x + threadIdx.x;
    const int stride = gridDim.x * blockDim.x;
    const int lane   = threadIdx.x & 31;
    const int wid    = threadIdx.x >> 5;
    const int nwarp  = blockDim.x >> 5;

    __shared__ float sh0[16], sh1[16];
    __shared__ float s_mu;

    // ---- Pass 1: sum g (64 MB DRAM stream; fills L2 with g) ----
    float s1 = 0.0f;
    #pragma unroll 4
    for (int i = tid; i < n4; i += stride) {
        float4 c = g[i];
        s1 += (c.x + c.y) + (c.z + c.w);
    }
    s1 = warp_reduce(s1);
    if (lane == 0) sh1[wid] = s1;
    __syncthreads();
    if (wid == 0) {
        float x1 = (lane < nwarp) ? sh1[lane] : 0.0f;
        x1 = warp_reduce(x1);
        if (lane == 0) atomicAdd(&g_acc[1], (double)x1);
    }

    // ---- Epoch grid barrier (monotone counter; replay-safe) ----
    if (threadIdx.x == 0) {
        __threadfence();
        unsigned int tkt    = atomicAdd(&g_bar[0], 1u);
        unsigned int target = (tkt / nCTA + 1u) * nCTA;
        while (*(volatile unsigned int*)&g_bar[0] < target) { __nanosleep(32); }
        double sum = *(volatile double*)&g_acc[1];
        s_mu = (float)(sum / ((double)n4 * 4.0));
    }
    __syncthreads();
    const float mu = s_mu;

    // ---- Pass 2: r,t from DRAM (evict-first) overlapped with g from L2 ----
    float s0 = 0.0f, s2 = 0.0f;
    #pragma unroll 2
    for (int i = tid; i < n4; i += stride) {
        float4 a = __ldcs(&r[i]);
        float4 b = __ldcs(&t[i]);
        float4 c = g[i];                 // should be an L2 hit
        s0 += fabsf(a.x - b.x) + fabsf(a.y - b.y) + fabsf(a.z - b.z) + fabsf(a.w - b.w);
        s2 += fabsf(c.x - mu) + fabsf(c.y - mu) + fabsf(c.z - mu) + fabsf(c.w - mu);
    }
    s0 = warp_reduce(s0);
    s2 = warp_reduce(s2);
    if (lane == 0) { sh0[wid] = s0; sh1[wid] = s2; }
    __syncthreads();
    if (wid == 0) {
        float x0 = (lane < nwarp) ? sh0[lane] : 0.0f;
        float x2 = (lane < nwarp) ? sh1[lane] : 0.0f;
        x0 = warp_reduce(x0);
        x2 = warp_reduce(x2);
        if (lane == 0) {
            atomicAdd(&g_acc[0], (double)x0);
            atomicAdd(&g_acc[2], (double)x2);
        }
    }

    // ---- Exit ticket: last CTA finalizes scalar + resets accumulators ----
    if (threadIdx.x == 0) {
        __threadfence();
        unsigned int tkt = atomicAdd(&g_bar[1], 1u);
        if ((tkt + 1u) % nCTA == 0u) {
            double a0  = *(volatile double*)&g_acc[0];
            double a2  = *(volatile double*)&g_acc[2];
            double n_d = (double)n4 * 4.0;
            out[0] = (float)((a0 + 100.0 * a2) / n_d);
            g_acc[0] = 0.0; g_acc[1] = 0.0; g_acc[2] = 0.0;  // ready for next replay
            __threadfence();
        }
    }
}

extern "C" void kernel_launch(void* const* d_in, const int* in_sizes, int n_in,
                              void* d_out, int out_size) {
    const float* resnet = (const float*)d_in[0];
    const float* gru    = (const float*)d_in[1];
    const float* target = (const float*)d_in[2];
    float* out = (float*)d_out;

    const int n  = in_sizes[0];
    const int n4 = n >> 2;

    const int block = 512;
    const unsigned int grid = 148u * 3u;   // 48 warps/SM

    k_fused<<<grid, block>>>((const float4*)resnet, (const float4*)target,
                             (const float4*)gru, out, n4, grid);
}

// round 8
// speedup vs baseline: 1.0010x; 1.0010x over previous
#include <cuda_runtime.h>

// Scratch: [0]=sum|r-t|, [1]=sum g, [2]=sum|g-mu|
// Zero at module load; reset by the exit-ticket CTA each run (replay-safe).
__device__ double g_acc[3];
// Monotone counters (never reset -> no reset/spin race across graph replays)
__device__ unsigned int g_bar[2];   // [0] mid grid barrier, [1] exit ticket

struct F8 { float v[8]; };

static __device__ __forceinline__ float warp_reduce(float v) {
    #pragma unroll
    for (int o = 16; o > 0; o >>= 1) v += __shfl_down_sync(0xFFFFFFFFu, v, o);
    return v;
}

// 32-byte load, lowest L2 priority (self-evicting stream: r, t)
static __device__ __forceinline__ F8 ld_ef(const float* p) {
    F8 r;
    asm("ld.global.nc.L2::evict_first.v8.b32 {%0,%1,%2,%3,%4,%5,%6,%7}, [%8];"
        : "=f"(r.v[0]), "=f"(r.v[1]), "=f"(r.v[2]), "=f"(r.v[3]),
          "=f"(r.v[4]), "=f"(r.v[5]), "=f"(r.v[6]), "=f"(r.v[7]) : "l"(p));
    return r;
}
// 32-byte load, highest L2 priority (pin g for the second pass)
static __device__ __forceinline__ F8 ld_el(const float* p) {
    F8 r;
    asm("ld.global.nc.L2::evict_last.v8.b32 {%0,%1,%2,%3,%4,%5,%6,%7}, [%8];"
        : "=f"(r.v[0]), "=f"(r.v[1]), "=f"(r.v[2]), "=f"(r.v[3]),
          "=f"(r.v[4]), "=f"(r.v[5]), "=f"(r.v[6]), "=f"(r.v[7]) : "l"(p));
    return r;
}
// plain 32-byte load (pass B; g expected in L2)
static __device__ __forceinline__ F8 ld_nc(const float* p) {
    F8 r;
    asm("ld.global.nc.v8.b32 {%0,%1,%2,%3,%4,%5,%6,%7}, [%8];"
        : "=f"(r.v[0]), "=f"(r.v[1]), "=f"(r.v[2]), "=f"(r.v[3]),
          "=f"(r.v[4]), "=f"(r.v[5]), "=f"(r.v[6]), "=f"(r.v[7]) : "l"(p));
    return r;
}

__global__ void __launch_bounds__(512, 3)
k_fused(const float* __restrict__ r, const float* __restrict__ t,
        const float* __restrict__ g, float* __restrict__ out,
        int n8, unsigned int nCTA) {
    const int tid    = blockIdx.x * blockDim.x + threadIdx.x;
    const int stride = gridDim.x * blockDim.x;
    const int lane   = threadIdx.x & 31;
    const int wid    = threadIdx.x >> 5;
    const int nwarp  = blockDim.x >> 5;

    __shared__ float sh0[16], sh1[16];
    __shared__ float s_mu;

    // ---- Pass A: one 192 MB stream. r/t evict-first, g pinned evict-last ----
    float s0 = 0.0f, s1 = 0.0f;
    for (int i = tid; i < n8; i += stride) {
        const long off = (long)i * 8;
        F8 a = ld_ef(r + off);
        F8 b = ld_ef(t + off);
        F8 c = ld_el(g + off);
        #pragma unroll
        for (int j = 0; j < 8; j++) {
            s0 += fabsf(a.v[j] - b.v[j]);
            s1 += c.v[j];
        }
    }
    s0 = warp_reduce(s0);
    s1 = warp_reduce(s1);
    if (lane == 0) { sh0[wid] = s0; sh1[wid] = s1; }
    __syncthreads();
    if (wid == 0) {
        float x0 = (lane < nwarp) ? sh0[lane] : 0.0f;
        float x1 = (lane < nwarp) ? sh1[lane] : 0.0f;
        x0 = warp_reduce(x0);
        x1 = warp_reduce(x1);
        if (lane == 0) {
            atomicAdd(&g_acc[0], (double)x0);
            atomicAdd(&g_acc[1], (double)x1);
        }
    }

    // ---- Epoch grid barrier (monotone counter; replay-safe) ----
    if (threadIdx.x == 0) {
        __threadfence();
        unsigned int tkt    = atomicAdd(&g_bar[0], 1u);
        unsigned int target = (tkt / nCTA + 1u) * nCTA;
        while (*(volatile unsigned int*)&g_bar[0] < target) { __nanosleep(32); }
        double sum = *(volatile double*)&g_acc[1];
        s_mu = (float)(sum / ((double)n8 * 8.0));
    }
    __syncthreads();
    const float mu = s_mu;

    // ---- Pass B: sum |g - mu| (g should now be a pinned L2 hit) ----
    float s2 = 0.0f;
    #pragma unroll 2
    for (int i = tid; i < n8; i += stride) {
        F8 c = ld_nc(g + (long)i * 8);
        #pragma unroll
        for (int j = 0; j < 8; j++) s2 += fabsf(c.v[j] - mu);
    }
    s2 = warp_reduce(s2);
    if (lane == 0) sh0[wid] = s2;
    __syncthreads();
    if (wid == 0) {
        float x2 = (lane < nwarp) ? sh0[lane] : 0.0f;
        x2 = warp_reduce(x2);
        if (lane == 0) atomicAdd(&g_acc[2], (double)x2);
    }

    // ---- Exit ticket: last CTA finalizes scalar + resets accumulators ----
    if (threadIdx.x == 0) {
        __threadfence();
        unsigned int tkt = atomicAdd(&g_bar[1], 1u);
        if ((tkt + 1u) % nCTA == 0u) {
            double a0  = *(volatile double*)&g_acc[0];
            double a2  = *(volatile double*)&g_acc[2];
            double n_d = (double)n8 * 8.0;
            out[0] = (float)((a0 + 100.0 * a2) / n_d);
            g_acc[0] = 0.0; g_acc[1] = 0.0; g_acc[2] = 0.0;  // ready for next replay
            __threadfence();
        }
    }
}

extern "C" void kernel_launch(void* const* d_in, const int* in_sizes, int n_in,
                              void* d_out, int out_size) {
    const float* resnet = (const float*)d_in[0];
    const float* gru    = (const float*)d_in[1];
    const float* target = (const float*)d_in[2];
    float* out = (float*)d_out;

    const int n  = in_sizes[0];
    const int n8 = n >> 3;               // 256-bit chunks

    const int block = 512;
    const unsigned int grid = 148u * 3u;   // 48 warps/SM

    k_fused<<<grid, block>>>(resnet, target, gru, out, n8, grid);
}

// round 9
// speedup vs baseline: 1.0087x; 1.0077x over previous
#include <cuda_runtime.h>

// Scratch: [0]=sum|r-t|, [1]=sum g, [2]=sum|g-mu|
// Zero at module load; reset by the exit-ticket CTA each run (replay-safe).
__device__ double g_acc[3];
// Monotone counters (never reset -> no reset/spin race across graph replays)
__device__ unsigned int g_bar[2];   // [0] mid grid barrier, [1] exit ticket

static __device__ __forceinline__ float warp_reduce(float v) {
    #pragma unroll
    for (int o = 16; o > 0; o >>= 1) v += __shfl_down_sync(0xFFFFFFFFu, v, o);
    return v;
}

__global__ void __launch_bounds__(512, 4)
k_fused(const float4* __restrict__ r, const float4* __restrict__ t,
        const float4* __restrict__ g, float* __restrict__ out,
        int n4, unsigned int nCTA) {
    const int tid    = blockIdx.x * blockDim.x + threadIdx.x;
    const int stride = gridDim.x * blockDim.x;
    const int lane   = threadIdx.x & 31;
    const int wid    = threadIdx.x >> 5;
    const int nwarp  = blockDim.x >> 5;

    __shared__ float sh0[16], sh1[16];
    __shared__ float s_mu;

    // ---- Pass A: one 192 MB stream: sum|r-t| and sum g ----
    float s0 = 0.0f, s1 = 0.0f;
    #pragma unroll 2
    for (int i = tid; i < n4; i += stride) {
        float4 a = __ldcs(&r[i]);      // streaming: evict-first-ish
        float4 b = __ldcs(&t[i]);
        float4 c = g[i];               // default: stays in L2 for pass B
        s0 += fabsf(a.x - b.x) + fabsf(a.y - b.y) + fabsf(a.z - b.z) + fabsf(a.w - b.w);
        s1 += (c.x + c.y) + (c.z + c.w);
    }
    s0 = warp_reduce(s0);
    s1 = warp_reduce(s1);
    if (lane == 0) { sh0[wid] = s0; sh1[wid] = s1; }
    __syncthreads();
    if (wid == 0) {
        float x0 = (lane < nwarp) ? sh0[lane] : 0.0f;
        float x1 = (lane < nwarp) ? sh1[lane] : 0.0f;
        x0 = warp_reduce(x0);
        x1 = warp_reduce(x1);
        if (lane == 0) {
            atomicAdd(&g_acc[0], (double)x0);
            atomicAdd(&g_acc[1], (double)x1);
        }
    }

    // ---- Epoch grid barrier (monotone counter; replay-safe) ----
    if (threadIdx.x == 0) {
        __threadfence();
        unsigned int tkt    = atomicAdd(&g_bar[0], 1u);
        unsigned int target = (tkt / nCTA + 1u) * nCTA;
        while (*(volatile unsigned int*)&g_bar[0] < target) { __nanosleep(32); }
        double sum = *(volatile double*)&g_acc[1];
        s_mu = (float)(sum / ((double)n4 * 4.0));
    }
    __syncthreads();
    const float mu = s_mu;

    // ---- Pass B: sum |g - mu| (mostly L2 hits) ----
    float s2 = 0.0f;
    #pragma unroll 4
    for (int i = tid; i < n4; i += stride) {
        float4 c = g[i];
        s2 += fabsf(c.x - mu) + fabsf(c.y - mu) + fabsf(c.z - mu) + fabsf(c.w - mu);
    }
    s2 = warp_reduce(s2);
    if (lane == 0) sh0[wid] = s2;
    __syncthreads();
    if (wid == 0) {
        float x2 = (lane < nwarp) ? sh0[lane] : 0.0f;
        x2 = warp_reduce(x2);
        if (lane == 0) atomicAdd(&g_acc[2], (double)x2);
    }

    // ---- Exit ticket: last CTA finalizes scalar + resets accumulators ----
    if (threadIdx.x == 0) {
        __threadfence();
        unsigned int tkt = atomicAdd(&g_bar[1], 1u);
        if ((tkt + 1u) % nCTA == 0u) {
            double a0  = *(volatile double*)&g_acc[0];
            double a2  = *(volatile double*)&g_acc[2];
            double n_d = (double)n4 * 4.0;
            out[0] = (float)((a0 + 100.0 * a2) / n_d);
            g_acc[0] = 0.0; g_acc[1] = 0.0; g_acc[2] = 0.0;  // ready for next replay
            __threadfence();
        }
    }
}

extern "C" void kernel_launch(void* const* d_in, const int* in_sizes, int n_in,
                              void* d_out, int out_size) {
    const float* resnet = (const float*)d_in[0];
    const float* gru    = (const float*)d_in[1];
    const float* target = (const float*)d_in[2];
    float* out = (float*)d_out;

    const int n  = in_sizes[0];
    const int n4 = n >> 2;

    const int block = 512;
    const unsigned int grid = 148u * 4u;   // 592 CTAs, 64 warps/SM, all co-resident

    k_fused<<<grid, block>>>((const float4*)resnet, (const float4*)target,
                             (const float4*)gru, out, n4, grid);
}